// round 16
// baseline (speedup 1.0000x reference)
#include <cuda_runtime.h>
#include <cuda_fp16.h>
#include <math.h>
#include <stdint.h>

// ---------------------------------------------------------------------------
// Problem constants
// ---------------------------------------------------------------------------
#define BB   8
#define LL   4096
#define CC   128
#define MROWS (BB*LL)      // 32768
#define SCALE_Q 0.17677669529663687f

// ---------------------------------------------------------------------------
// Scratch (device globals — no allocation allowed)
// ---------------------------------------------------------------------------
__device__ float g_buf  [MROWS * CC];        // fp32 running state g
__device__ float g_t1   [MROWS * CC];        // t1 in phase 4
__device__ float g_off  [BB * 3 * LL];
__device__ float g_msk  [BB * 3 * LL];

// fp16 activation buffers
__device__ __align__(256) __half g_A16[MROWS * 256];   // concat input / attn out / fu
__device__ __align__(256) __half g_B16[MROWS * 512];   // qkv (384) / FFN hidden (512)
__device__ __align__(256) __half g_C16[MROWS * 128];   // LN outputs / g fp16 copy
__device__ __align__(256) __half g_D16[MROWS * 128];   // deform output (local branch)

// converted + transposed weights, fp16 [N][K]
__device__ __align__(256) __half w_red[128*256];
__device__ __align__(256) __half w_qkv[2][384*128];
__device__ __align__(256) __half w_pw [2][128*128];
__device__ __align__(256) __half w_f1 [2][512*128];
__device__ __align__(256) __half w_f2 [2][128*512];
__device__ __align__(256) __half w_lf[128*128];
__device__ __align__(256) __half w_gf[128*128];
__device__ __align__(256) __half w_ff[128*128];

// ---------------------------------------------------------------------------
// helpers
// ---------------------------------------------------------------------------
__device__ __forceinline__ uint32_t smem_u32(const void* p) {
    uint32_t a;
    asm("{ .reg .u64 t; cvta.to.shared.u64 t, %1; cvt.u32.u64 %0, t; }"
        : "=r"(a) : "l"(p));
    return a;
}
__device__ __forceinline__ void cp16(uint32_t s, const void* g) {
    asm volatile("cp.async.cg.shared.global [%0], [%1], 16;" :: "r"(s), "l"(g));
}
__device__ __forceinline__ uint32_t pack2h(float a, float b) {
    __half2 p = __floats2half2_rn(a, b);
    return *(uint32_t*)&p;
}

#define LDSM4(r, a) \
    asm volatile("ldmatrix.sync.aligned.m8n8.x4.shared.b16 {%0,%1,%2,%3}, [%4];" \
        : "=r"((r)[0]), "=r"((r)[1]), "=r"((r)[2]), "=r"((r)[3]) : "r"(a))

#define MMA16816(d, a, b0, b1) \
    asm volatile("mma.sync.aligned.m16n8k16.row.col.f32.f16.f16.f32 " \
        "{%0,%1,%2,%3}, {%4,%5,%6,%7}, {%8,%9}, {%0,%1,%2,%3};" \
        : "+f"((d)[0]), "+f"((d)[1]), "+f"((d)[2]), "+f"((d)[3]) \
        : "r"((a)[0]), "r"((a)[1]), "r"((a)[2]), "r"((a)[3]), "r"(b0), "r"(b1))

// warp LN of one 128-col row: lanes hold 4 consecutive values each
__device__ __forceinline__ void warp_ln_stats(float4 v, float& mean, float& rstd) {
    float sum = v.x + v.y + v.z + v.w;
    float sq  = v.x * v.x + v.y * v.y + v.z * v.z + v.w * v.w;
#pragma unroll
    for (int o = 16; o; o >>= 1) {
        sum += __shfl_xor_sync(0xffffffffu, sum, o);
        sq  += __shfl_xor_sync(0xffffffffu, sq, o);
    }
    mean = sum * (1.0f / 128.0f);
    float var = sq * (1.0f / 128.0f) - mean * mean;
    rstd = rsqrtf(var + 1e-5f);
}

// ---------------------------------------------------------------------------
// Epilogues: ep(m, n0, N, float4), n0 % 4 == 0.
// Contract: one warp processes one full output row (32 lanes x float4),
// convergent — warp shuffles are legal inside.
// ---------------------------------------------------------------------------
struct EpiBias {
    float* out; const float* bias;
    __device__ __forceinline__ void operator()(int m, int n0, int N, float4 v) const {
        const float4 b = *(const float4*)&bias[n0];
        v.x += b.x; v.y += b.y; v.z += b.z; v.w += b.w;
        *(float4*)&out[(size_t)m * N + n0] = v;
    }
};
struct EpiBiasH {     // acc + bias -> fp16
    __half* out; const float* bias;
    __device__ __forceinline__ void operator()(int m, int n0, int N, float4 v) const {
        const float4 b = *(const float4*)&bias[n0];
        uint2 o;
        o.x = pack2h(v.x + b.x, v.y + b.y);
        o.y = pack2h(v.z + b.z, v.w + b.w);
        *(uint2*)&out[(size_t)m * N + n0] = o;
    }
};
// acc + bias -> g (fp32) ; LN + roll-partition permute -> a16 (fp16)
struct EpiBiasLN {
    float* g; const float* bias;
    __half* a16; const float* lng; const float* lnb; int shift;
    __device__ __forceinline__ void operator()(int m, int n0, int N, float4 v) const {
        const float4 b = *(const float4*)&bias[n0];
        v.x += b.x; v.y += b.y; v.z += b.z; v.w += b.w;
        *(float4*)&g[(size_t)m * CC + n0] = v;
        float mean, rstd; warp_ln_stats(v, mean, rstd);
        const float4 G  = *(const float4*)&lng[n0];
        const float4 Bt = *(const float4*)&lnb[n0];
        int bb = m >> 12, hw = m & 4095;
        int hp = ((hw >> 6) - shift) & 63;
        int wp = ((hw & 63) - shift) & 63;
        int dst = (bb << 12) + ((((hp >> 3) << 3) + (wp >> 3)) << 6)
                + ((hp & 7) << 3) + (wp & 7);
        uint2 o;
        o.x = pack2h((v.x - mean) * rstd * G.x + Bt.x, (v.y - mean) * rstd * G.y + Bt.y);
        o.y = pack2h((v.z - mean) * rstd * G.z + Bt.z, (v.w - mean) * rstd * G.w + Bt.w);
        *(uint2*)&a16[(size_t)dst * CC + n0] = o;
    }
};
// res + acc + bias -> g ; LN + roll-partition permute -> a16
struct EpiResidLN {
    float* g; const float* res; const float* bias;
    __half* a16; const float* lng; const float* lnb; int shift;
    __device__ __forceinline__ void operator()(int m, int n0, int N, float4 v) const {
        size_t i = (size_t)m * CC + n0;
        const float4 b = *(const float4*)&bias[n0];
        const float4 r = *(const float4*)&res[i];
        v.x += b.x + r.x; v.y += b.y + r.y; v.z += b.z + r.z; v.w += b.w + r.w;
        *(float4*)&g[i] = v;
        float mean, rstd; warp_ln_stats(v, mean, rstd);
        const float4 G  = *(const float4*)&lng[n0];
        const float4 Bt = *(const float4*)&lnb[n0];
        int bb = m >> 12, hw = m & 4095;
        int hp = ((hw >> 6) - shift) & 63;
        int wp = ((hw & 63) - shift) & 63;
        int dst = (bb << 12) + ((((hp >> 3) << 3) + (wp >> 3)) << 6)
                + ((hp & 7) << 3) + (wp & 7);
        uint2 o;
        o.x = pack2h((v.x - mean) * rstd * G.x + Bt.x, (v.y - mean) * rstd * G.y + Bt.y);
        o.y = pack2h((v.z - mean) * rstd * G.z + Bt.z, (v.w - mean) * rstd * G.w + Bt.w);
        *(uint2*)&a16[(size_t)dst * CC + n0] = o;
    }
};
struct EpiResidH {  // (res + acc + bias) -> fp16
    __half* out; const float* res; const float* bias;
    __device__ __forceinline__ void operator()(int m, int n0, int N, float4 v) const {
        size_t i = (size_t)m * N + n0;
        const float4 b = *(const float4*)&bias[n0];
        const float4 r = *(const float4*)&res[i];
        uint2 o;
        o.x = pack2h(v.x + b.x + r.x, v.y + b.y + r.y);
        o.y = pack2h(v.z + b.z + r.z, v.w + b.w + r.w);
        *(uint2*)&out[i] = o;
    }
};
// window-reverse(+shift) residual RMW into g ; LN -> a16 (token layout)
struct EpiProjLN {
    float* g; const float* bias; int shift;
    __half* a16; const float* lng; const float* lnb;
    __device__ __forceinline__ void operator()(int m, int n0, int N, float4 v) const {
        int bb   = m >> 12;
        int rb   = m & 4095;
        int widx = rb >> 6;
        int tok  = rb & 63;
        int hh = ((widx >> 3) << 3) + (tok >> 3);
        int ww = ((widx & 7) << 3) + (tok & 7);
        int h = (hh + shift) & 63;
        int w = (ww + shift) & 63;
        size_t dst = (size_t)(bb << 12) + (h << 6) + w;
        size_t di = dst * CC + n0;
        const float4 bi = *(const float4*)&bias[n0];
        float4 o = *(const float4*)&g[di];
        o.x += v.x + bi.x; o.y += v.y + bi.y; o.z += v.z + bi.z; o.w += v.w + bi.w;
        *(float4*)&g[di] = o;
        float mean, rstd; warp_ln_stats(o, mean, rstd);
        const float4 G  = *(const float4*)&lng[n0];
        const float4 Bt = *(const float4*)&lnb[n0];
        uint2 ov;
        ov.x = pack2h((o.x - mean) * rstd * G.x + Bt.x, (o.y - mean) * rstd * G.y + Bt.y);
        ov.y = pack2h((o.z - mean) * rstd * G.z + Bt.z, (o.w - mean) * rstd * G.w + Bt.w);
        *(uint2*)&a16[di] = ov;
    }
};
struct EpiGeluH {
    __half* out; const float* bias;
    __device__ __forceinline__ void operator()(int m, int n0, int N, float4 v) const {
        const float4 b = *(const float4*)&bias[n0];
        float g[4] = {v.x + b.x, v.y + b.y, v.z + b.z, v.w + b.w};
#pragma unroll
        for (int k = 0; k < 4; k++)
            g[k] = 0.5f * g[k] * (1.0f + erff(g[k] * 0.7071067811865476f));
        uint2 o; o.x = pack2h(g[0], g[1]); o.y = pack2h(g[2], g[3]);
        *(uint2*)&out[(size_t)m * N + n0] = o;
    }
};
struct EpiMulReluH {
    __half* out; const float* t1; const float* bias;
    __device__ __forceinline__ void operator()(int m, int n0, int N, float4 v) const {
        size_t i = (size_t)m * N + n0;
        const float4 b = *(const float4*)&bias[n0];
        const float4 t = *(const float4*)&t1[i];
        float g[4] = {fmaxf(0.0f, t.x * (v.x + b.x)), fmaxf(0.0f, t.y * (v.y + b.y)),
                      fmaxf(0.0f, t.z * (v.z + b.z)), fmaxf(0.0f, t.w * (v.w + b.w))};
        uint2 o; o.x = pack2h(g[0], g[1]); o.y = pack2h(g[2], g[3]);
        *(uint2*)&out[i] = o;
    }
};
struct EpiLSTM {
    float* hy; const float* cx; const float* bias;
    __device__ __forceinline__ void operator()(int m, int n0, int N, float4 v) const {
        size_t i = (size_t)m * N + n0;
        const float4 b = *(const float4*)&bias[n0];
        const float4 c = *(const float4*)&cx[i];
        float f[4] = {v.x + b.x, v.y + b.y, v.z + b.z, v.w + b.w};
        float cc[4] = {c.x, c.y, c.z, c.w};
        float o[4];
#pragma unroll
        for (int k = 0; k < 4; k++) {
            float gate = 1.0f / (1.0f + expf(-f[k]));
            float cell = tanhf(f[k]);
            float cy   = gate * (cc[k] + cell);
            o[k] = gate * tanhf(cy);
        }
        *(float4*)&hy[i] = *(float4*)o;
    }
};

// ---------------------------------------------------------------------------
// fp16 single-pass GEMM on mma.sync (m16n8k16): D = A @ W.
// CTA tile 128x128, 8 warps (4m x 2n), K-chunk 64, 2-stage cp.async pipeline.
// ---------------------------------------------------------------------------
#define TSTRIDE 144
#define TILE_B  18432     // 128 rows * 144
#define STAGE_B 36864     // A tile + W tile
#define SOUT_STRIDE 132
#define GEMM_SMEM 73728   // max(2*STAGE_B=73728, sout 128*132*4=67584)

__device__ __forceinline__ void mma_mainloop(
    const __half* __restrict__ A, const __half* __restrict__ W,
    int K, int bm, int bn, uint32_t sb, int tid, float acc[2][8][4])
{
    const int wid = tid >> 5, lane = tid & 31;
    const int mw = wid & 3, nw = wid >> 2;
    const int nch = K >> 6;

    auto load_stage = [&](int i) {
        uint32_t st = sb + (uint32_t)(i & 1) * STAGE_B;
        int kt = i << 6;
#pragma unroll
        for (int k = 0; k < 4; k++) {
            int e = tid + k * 256;
            int r = e >> 3, q = e & 7;
            uint32_t so = (uint32_t)r * TSTRIDE + q * 16;
            cp16(st + so,          A + (size_t)(bm + r) * K + kt + q * 8);
            cp16(st + TILE_B + so, W + (size_t)(bn + r) * K + kt + q * 8);
        }
        asm volatile("cp.async.commit_group;");
    };

    load_stage(0);
    if (nch > 1) load_stage(1);

    for (int i = 0; i < nch; i++) {
        if (i + 1 < nch) asm volatile("cp.async.wait_group 1;");
        else             asm volatile("cp.async.wait_group 0;");
        __syncthreads();

        uint32_t st = sb + (uint32_t)(i & 1) * STAGE_B;
#pragma unroll
        for (int j = 0; j < 4; j++) {
            uint32_t a[2][4], bh[4][4];
#pragma unroll
            for (int mt = 0; mt < 2; mt++) {
                uint32_t addr = st +
                    (uint32_t)((mw << 5) + (mt << 4) + (lane & 15)) * TSTRIDE +
                    (j << 5) + ((lane >> 4) << 4);
                LDSM4(a[mt], addr);
            }
#pragma unroll
            for (int nb = 0; nb < 4; nb++) {
                uint32_t addr = st + TILE_B +
                    (uint32_t)((nw << 6) + (nb << 4) + (lane & 7) + ((lane >> 4) << 3)) * TSTRIDE +
                    (j << 5) + (((lane >> 3) & 1) << 4);
                LDSM4(bh[nb], addr);
            }
#pragma unroll
            for (int mt = 0; mt < 2; mt++)
#pragma unroll
                for (int nt = 0; nt < 8; nt++)
                    MMA16816(acc[mt][nt], a[mt],
                             bh[nt >> 1][(nt & 1) * 2], bh[nt >> 1][(nt & 1) * 2 + 1]);
        }

        if (i + 2 < nch) {
            __syncthreads();
            load_stage(i + 2);
        }
    }
    __syncthreads();
}

template <class EP>
__global__ __launch_bounds__(256, 2)
void gemm_mma(const __half* __restrict__ A, const __half* __restrict__ W,
              int K, int Nfull, EP ep) {
    extern __shared__ char sm[];
    const int tid  = threadIdx.x;
    const int wid  = tid >> 5;
    const int lane = tid & 31;
    const int mw = wid & 3, nw = wid >> 2;
    const int bm = blockIdx.y * 128;
    const int bn = blockIdx.x * 128;
    const uint32_t sb = smem_u32(sm);

    float acc[2][8][4];
#pragma unroll
    for (int a = 0; a < 2; a++)
#pragma unroll
        for (int b = 0; b < 8; b++)
#pragma unroll
            for (int c = 0; c < 4; c++) acc[a][b][c] = 0.0f;

    mma_mainloop(A, W, K, bm, bn, sb, tid, acc);

    float* sout = (float*)sm;
    const int mb = mw << 5, nb = nw << 6;
#pragma unroll
    for (int mt = 0; mt < 2; mt++)
#pragma unroll
        for (int nt = 0; nt < 8; nt++)
#pragma unroll
            for (int rg = 0; rg < 4; rg++) {
                int ml = mb + (mt << 4) + (lane >> 2) + ((rg >> 1) << 3);
                int nl = nb + (nt << 3) + ((lane & 3) << 1) + (rg & 1);
                sout[ml * SOUT_STRIDE + nl] = acc[mt][nt][rg];
            }
    __syncthreads();
#pragma unroll 4
    for (int e = tid; e < 4096; e += 256) {
        int r = e >> 5, c4 = (e & 31) << 2;
        float4 v = *(float4*)&sout[r * SOUT_STRIDE + c4];
        ep(bm + r, bn + c4, Nfull, v);
    }
}

// ---------------------------------------------------------------------------
// Combined weight transpose + fp16 convert: 12 jobs in one launch
// ---------------------------------------------------------------------------
struct WJob { const float* src; __half* dst; int K, N, start; };
struct WJobs { WJob j[12]; int total; };

__global__ void wcvt_all(WJobs js) {
    int idx = blockIdx.x * 256 + threadIdx.x;
    if (idx >= js.total) return;
    int jj = 0;
#pragma unroll
    for (int t = 1; t < 12; t++) if (idx >= js.j[t].start) jj = t;
    const WJob J = js.j[jj];
    int local = idx - J.start;
    int k = local / J.N, n = local - k * J.N;
    J.dst[(size_t)n * J.K + k] = __float2half(J.src[local]);
}

// concat(xt,hx) -> A16 [M][256]
__global__ void cvtcat_kernel(const float* __restrict__ x, const float* __restrict__ hsrc,
                              __half* __restrict__ o) {
    int i = blockIdx.x * 256 + threadIdx.x;
    int m = i >> 7, k = i & 127;
    o[(size_t)m * 256 + k]       = __float2half(x[i]);
    o[(size_t)m * 256 + 128 + k] = __float2half(hsrc[i]);
}

// ---------------------------------------------------------------------------
// Window attention, qkv in fp16 -> fp16 output.
// Block = one window (256 thr = 4 heads x 64 rows)
// ---------------------------------------------------------------------------
__device__ __forceinline__ int zone_(int h) { return h < 56 ? 0 : (h < 60 ? 1 : 2); }

#define ATTN_SMEM 69136   // kk 32KB + vv 32KB + rps 3600B

__global__ __launch_bounds__(256)
void attn_kernel(const __half* __restrict__ qkv, const float* __restrict__ rp,
                 __half* __restrict__ out, int shift) {
    extern __shared__ float smf[];
    float* kk  = smf;
    float* vv  = smf + 8192;
    float* rps = smf + 16384;

    const int wi   = blockIdx.x;
    const int t    = threadIdx.x;
    const int head = t >> 6;
    const int row  = t & 63;
    const int base = wi * 64;

    for (int i = t; i < 900; i += 256) rps[i] = rp[i];
    for (int i = t; i < 4096; i += 256) {
        int m = i >> 6, c2 = (i & 63) << 1;
        __half2 hk = *(const __half2*)&qkv[(size_t)(base + m) * 384 + 128 + c2];
        __half2 hv = *(const __half2*)&qkv[(size_t)(base + m) * 384 + 256 + c2];
        float2 fk = __half22float2(hk);
        float2 fv = __half22float2(hv);
        int part = c2 >> 5, off = c2 & 31;
        kk[(part * 64 + m) * 32 + off]     = fk.x;
        kk[(part * 64 + m) * 32 + off + 1] = fk.y;
        vv[(part * 64 + m) * 32 + off]     = fv.x;
        vv[(part * 64 + m) * 32 + off + 1] = fv.y;
    }
    __syncthreads();

    float q[32];
#pragma unroll
    for (int d8 = 0; d8 < 4; d8++) {
        uint4 raw = *(const uint4*)&qkv[(size_t)(base + row) * 384 + head * 32 + d8 * 8];
        const __half2* hp = (const __half2*)&raw;
#pragma unroll
        for (int p = 0; p < 4; p++) {
            float2 f = __half22float2(hp[p]);
            q[d8*8 + p*2]     = f.x * SCALE_Q;
            q[d8*8 + p*2 + 1] = f.y * SCALE_Q;
        }
    }

    const int rn = row >> 3, cn = row & 7;
    const int widx = wi & 63;
    const int wh = widx >> 3, wwc = widx & 7;
    int zr_n = 0, zc_n = 0;
    if (shift) { zr_n = zone_(wh * 8 + rn); zc_n = zone_(wwc * 8 + cn); }

    const float* kh = kk + head * 2048;
    const float* vh = vv + head * 2048;

    float o[32];
#pragma unroll
    for (int d = 0; d < 32; d++) o[d] = 0.0f;
    float sum = 0.0f;

#pragma unroll 4
    for (int m = 0; m < 64; m++) {
        float a = 0.0f;
        const float* kr = kh + m * 32;
#pragma unroll
        for (int d4 = 0; d4 < 8; d4++) {
            float4 kv4 = *(const float4*)&kr[d4 * 4];
            a += q[d4*4+0] * kv4.x + q[d4*4+1] * kv4.y +
                 q[d4*4+2] * kv4.z + q[d4*4+3] * kv4.w;
        }
        int rm = m >> 3, cm = m & 7;
        int ridx = (rn - rm + 7) * 15 + (cn - cm + 7);
        a += rps[ridx * 4 + head];
        if (shift) {
            if (zone_(wh * 8 + rm) != zr_n || zone_(wwc * 8 + cm) != zc_n)
                a += -100.0f;
        }
        float p = __expf(a);
        sum += p;
        const float* vr = vh + m * 32;
#pragma unroll
        for (int d4 = 0; d4 < 8; d4++) {
            float4 vv4 = *(const float4*)&vr[d4 * 4];
            o[d4*4+0] += p * vv4.x; o[d4*4+1] += p * vv4.y;
            o[d4*4+2] += p * vv4.z; o[d4*4+3] += p * vv4.w;
        }
    }
    float inv = 1.0f / sum;
#pragma unroll
    for (int d4 = 0; d4 < 8; d4++) {
        uint2 ov;
        ov.x = pack2h(o[d4*4+0] * inv, o[d4*4+1] * inv);
        ov.y = pack2h(o[d4*4+2] * inv, o[d4*4+3] * inv);
        *(uint2*)&out[(size_t)(base + row) * CC + head * 32 + d4 * 4] = ov;
    }
}

// ---------------------------------------------------------------------------
// Conv1d offset + mask head: 32 positions per block (weight load amortized)
// ---------------------------------------------------------------------------
__global__ void offmask_kernel(const float* __restrict__ xt,
                               const float* __restrict__ offw, const float* __restrict__ offb,
                               const float* __restrict__ mskw, const float* __restrict__ mskb,
                               float* __restrict__ off, float* __restrict__ msk) {
    __shared__ float swo[1152], swm[1152];
    int tid = threadIdx.x;
    for (int i = tid; i < 1152; i += 256) { swo[i] = offw[i]; swm[i] = mskw[i]; }
    __syncthreads();

    int warp = tid >> 5, lane = tid & 31;
    int pos0 = blockIdx.x * 32 + warp * 4;

    for (int pp = 0; pp < 4; pp++) {
        int pos = pos0 + pp;
        int b = pos >> 12, l = pos & 4095;

        float ao[3] = {0.f, 0.f, 0.f}, am[3] = {0.f, 0.f, 0.f};
#pragma unroll
        for (int i = 0; i < 4; i++) {
            int c = lane + 32 * i;
            float xv[3];
#pragma unroll
            for (int j = 0; j < 3; j++) {
                int ls = l + j - 1;
                xv[j] = (ls >= 0 && ls < LL)
                      ? xt[((size_t)(b << 12) + ls) * CC + c] : 0.0f;
            }
#pragma unroll
            for (int ko = 0; ko < 3; ko++)
#pragma unroll
                for (int j = 0; j < 3; j++) {
                    ao[ko] += xv[j] * swo[ko * 384 + c * 3 + j];
                    am[ko] += xv[j] * swm[ko * 384 + c * 3 + j];
                }
        }
#pragma unroll
        for (int o = 16; o; o >>= 1)
#pragma unroll
            for (int ko = 0; ko < 3; ko++) {
                ao[ko] += __shfl_xor_sync(0xffffffffu, ao[ko], o);
                am[ko] += __shfl_xor_sync(0xffffffffu, am[ko], o);
            }
        if (lane == 0) {
#pragma unroll
            for (int ko = 0; ko < 3; ko++) {
                float ov = ao[ko] + offb[ko];
                float mv = am[ko] + mskb[ko];
                off[((size_t)(b * 3 + ko)) * LL + l] = ov;
                msk[((size_t)(b * 3 + ko)) * LL + l] = 1.0f / (1.0f + expf(-mv));
            }
        }
    }
}

// ---------------------------------------------------------------------------
// Deformable sample -> fp16 at flat (B,C,L) layout == (B,L,C) view
// ---------------------------------------------------------------------------
__global__ void deform_kernel(const float* __restrict__ xt,
                              const float* __restrict__ off,
                              const float* __restrict__ msk,
                              __half* __restrict__ out) {
    __shared__ float s[128][33];
    __shared__ int   sfp[3][32], scp[3][32];
    __shared__ float sal[3][32], sm[3][32];

    int blk = blockIdx.x;
    int b = blk >> 7;
    int l0 = (blk & 127) << 5;
    int tid = threadIdx.x;

    if (tid < 96) {
        int k = tid / 32, li = tid % 32;
        int l = l0 + li;
        float o  = off[((size_t)(b * 3 + k)) * LL + l];
        float p  = fminf(fmaxf((float)l + o, 0.0f), 4095.0f);
        int fp   = (int)floorf(p);
        int cp   = min(fp + 1, 4095);
        sfp[k][li] = fp; scp[k][li] = cp;
        sal[k][li] = p - (float)fp;
        sm [k][li] = msk[((size_t)(b * 3 + k)) * LL + l];
    }
    __syncthreads();

    for (int e = tid; e < 4096; e += 256) {
        int li = e >> 7, c = e & 127;
        float acc = 0.0f;
#pragma unroll
        for (int k = 0; k < 3; k++) {
            float a  = sal[k][li];
            float xf = xt[((size_t)(b << 12) + sfp[k][li]) * CC + c];
            float xc = xt[((size_t)(b << 12) + scp[k][li]) * CC + c];
            acc += (xf * (1.0f - a) + xc * a) * sm[k][li];
        }
        s[c][li] = acc;
    }
    __syncthreads();
    for (int e = tid; e < 4096; e += 256) {
        int c = e >> 5, li = e & 31;
        size_t idx = (size_t)b * (CC * LL) + (size_t)c * LL + l0 + li;
        out[idx] = __float2half(s[c][li]);
    }
}

// ---------------------------------------------------------------------------
// Host launch
// ---------------------------------------------------------------------------
extern "C" void kernel_launch(void* const* d_in, const int* in_sizes, int n_in,
                              void* d_out, int out_size) {
    const float* xt    = (const float*)d_in[0];
    const float* hx    = (const float*)d_in[1];
    const float* cx    = (const float*)d_in[2];
    const float* red_w = (const float*)d_in[3];
    const float* red_b = (const float*)d_in[4];
    const float* n1g   = (const float*)d_in[5];
    const float* n1b   = (const float*)d_in[6];
    const float* qkvw  = (const float*)d_in[7];
    const float* qkvb  = (const float*)d_in[8];
    const float* rp    = (const float*)d_in[9];
    const float* pw    = (const float*)d_in[10];
    const float* pb    = (const float*)d_in[11];
    const float* n2g   = (const float*)d_in[12];
    const float* n2b   = (const float*)d_in[13];
    const float* f1w   = (const float*)d_in[14];
    const float* f1b   = (const float*)d_in[15];
    const float* f2w   = (const float*)d_in[16];
    const float* f2b   = (const float*)d_in[17];
    const float* off_w = (const float*)d_in[18];
    const float* off_b = (const float*)d_in[19];
    const float* msk_w = (const float*)d_in[20];
    const float* msk_b = (const float*)d_in[21];
    const float* lf_w  = (const float*)d_in[22];
    const float* lf_b  = (const float*)d_in[23];
    const float* gf_w  = (const float*)d_in[24];
    const float* gf_b  = (const float*)d_in[25];
    const float* ff_w  = (const float*)d_in[26];
    const float* ff_b  = (const float*)d_in[27];
    float* hy = (float*)d_out;

    float *pg, *pt1, *poff, *pmsk;
    cudaGetSymbolAddress((void**)&pg,   g_buf);
    cudaGetSymbolAddress((void**)&pt1,  g_t1);
    cudaGetSymbolAddress((void**)&poff, g_off);
    cudaGetSymbolAddress((void**)&pmsk, g_msk);

    __half *A16, *B16, *C16, *D16;
    cudaGetSymbolAddress((void**)&A16, g_A16);
    cudaGetSymbolAddress((void**)&B16, g_B16);
    cudaGetSymbolAddress((void**)&C16, g_C16);
    cudaGetSymbolAddress((void**)&D16, g_D16);

    __half *redw, *qkvw16, *pww, *f1ww, *f2ww, *lfw, *gfw, *ffw;
    cudaGetSymbolAddress((void**)&redw,   w_red);
    cudaGetSymbolAddress((void**)&qkvw16, w_qkv);
    cudaGetSymbolAddress((void**)&pww,    w_pw);
    cudaGetSymbolAddress((void**)&f1ww,   w_f1);
    cudaGetSymbolAddress((void**)&f2ww,   w_f2);
    cudaGetSymbolAddress((void**)&lfw,    w_lf);
    cudaGetSymbolAddress((void**)&gfw,    w_gf);
    cudaGetSymbolAddress((void**)&ffw,    w_ff);

    cudaFuncSetAttribute(gemm_mma<EpiBias>,     cudaFuncAttributeMaxDynamicSharedMemorySize, GEMM_SMEM);
    cudaFuncSetAttribute(gemm_mma<EpiBiasH>,    cudaFuncAttributeMaxDynamicSharedMemorySize, GEMM_SMEM);
    cudaFuncSetAttribute(gemm_mma<EpiBiasLN>,   cudaFuncAttributeMaxDynamicSharedMemorySize, GEMM_SMEM);
    cudaFuncSetAttribute(gemm_mma<EpiGeluH>,    cudaFuncAttributeMaxDynamicSharedMemorySize, GEMM_SMEM);
    cudaFuncSetAttribute(gemm_mma<EpiProjLN>,   cudaFuncAttributeMaxDynamicSharedMemorySize, GEMM_SMEM);
    cudaFuncSetAttribute(gemm_mma<EpiResidLN>,  cudaFuncAttributeMaxDynamicSharedMemorySize, GEMM_SMEM);
    cudaFuncSetAttribute(gemm_mma<EpiResidH>,   cudaFuncAttributeMaxDynamicSharedMemorySize, GEMM_SMEM);
    cudaFuncSetAttribute(gemm_mma<EpiMulReluH>, cudaFuncAttributeMaxDynamicSharedMemorySize, GEMM_SMEM);
    cudaFuncSetAttribute(gemm_mma<EpiLSTM>,     cudaFuncAttributeMaxDynamicSharedMemorySize, GEMM_SMEM);
    cudaFuncSetAttribute(attn_kernel,           cudaFuncAttributeMaxDynamicSharedMemorySize, ATTN_SMEM);

    const dim3 blk256(256);

    // side stream + fork/join events for the independent local branch.
    // Created fresh per call (kernel_launch runs only for correctness + capture;
    // objects are intentionally leaked — no device-memory allocation involved).
    cudaStream_t s2;
    cudaStreamCreateWithFlags(&s2, cudaStreamNonBlocking);
    cudaEvent_t evFork, evJoin;
    cudaEventCreateWithFlags(&evFork, cudaEventDisableTiming);
    cudaEventCreateWithFlags(&evJoin, cudaEventDisableTiming);

    // 0) all weight converts in one launch (main stream)
    {
        WJobs js; int off = 0, n = 0;
        auto add = [&](const float* s, __half* d, int K, int N) {
            js.j[n++] = WJob{s, d, K, N, off};
            off += K * N;
        };
        add(red_w, redw, 256, 128);
        for (int i = 0; i < 2; i++) {
            add(qkvw + (size_t)i*128*384, qkvw16 + (size_t)i*384*128, 128, 384);
            add(pw   + (size_t)i*128*128, pww    + (size_t)i*128*128, 128, 128);
            add(f1w  + (size_t)i*128*512, f1ww   + (size_t)i*512*128, 128, 512);
            add(f2w  + (size_t)i*512*128, f2ww   + (size_t)i*128*512, 512, 128);
        }
        add(lf_w, lfw, 128, 128);
        add(gf_w, gfw, 128, 128);
        add(ff_w, ffw, 128, 128);
        js.total = off;
        wcvt_all<<<(off + 255) / 256, blk256>>>(js);
    }

    // fork: local branch (offmask -> deform -> lf GEMM) on s2
    cudaEventRecord(evFork, 0);
    cudaStreamWaitEvent(s2, evFork, 0);
    offmask_kernel<<<MROWS / 32, blk256, 0, s2>>>(xt, off_w, off_b, msk_w, msk_b,
                                                  poff, pmsk);
    deform_kernel<<<BB * (LL / 32), blk256, 0, s2>>>(xt, poff, pmsk, D16);
    gemm_mma<<<dim3(1, 256), blk256, GEMM_SMEM, s2>>>(D16, lfw, 128, 128,
                                                      EpiBias{pt1, lf_b});
    cudaEventRecord(evJoin, s2);

    const dim3 gN1(1, 256), gN3(3, 256), gN4(4, 256);

    // 1) g = concat(xt, hx) @ red_w + red_b ; fused ln1(shift=0) -> C16
    cvtcat_kernel<<<MROWS * 128 / 256, blk256>>>(xt, hx, A16);
    gemm_mma<<<gN1, blk256, GEMM_SMEM>>>(A16, redw, 256, 128,
        EpiBiasLN{pg, red_b, C16, n1g, n1b, 0});

    // 2) two Swin blocks (LNs fused into GEMM epilogues)
    for (int i = 0; i < 2; i++) {
        int shift = (i == 0) ? 0 : 4;
        const float* qkvb_i = qkvb + (size_t)i * 384;
        const float* rp_i   = rp   + (size_t)i * 225 * 4;
        const float* pb_i   = pb   + (size_t)i * 128;
        const float* f1b_i  = f1b  + (size_t)i * 512;
        const float* f2b_i  = f2b  + (size_t)i * 128;

        gemm_mma<<<gN3, blk256, GEMM_SMEM>>>(C16, qkvw16 + (size_t)i*384*128,
                                             128, 384, EpiBiasH{B16, qkvb_i});
        attn_kernel<<<BB * 64, blk256, ATTN_SMEM>>>(B16, rp_i, A16, shift);
        gemm_mma<<<gN1, blk256, GEMM_SMEM>>>(A16, pww + (size_t)i*128*128, 128, 128,
            EpiProjLN{pg, pb_i, shift, C16, n2g + i * CC, n2b + i * CC});
        gemm_mma<<<gN4, blk256, GEMM_SMEM>>>(C16, f1ww + (size_t)i*512*128,
                                             128, 512, EpiGeluH{B16, f1b_i});
        if (i == 0)
            gemm_mma<<<gN1, blk256, GEMM_SMEM>>>(B16, f2ww, 512, 128,
                EpiResidLN{pg, pg, f2b_i, C16, n1g + CC, n1b + CC, 4});
        else
            gemm_mma<<<gN1, blk256, GEMM_SMEM>>>(B16, f2ww + (size_t)1*128*512,
                                                 512, 128, EpiResidH{C16, pg, f2b_i});
    }

    // join: need t1 (from s2) before gf epilogue
    cudaStreamWaitEvent(0, evJoin, 0);

    // 4) fusion + LSTM gating
    gemm_mma<<<gN1, blk256, GEMM_SMEM>>>(C16, gfw, 128, 128, EpiMulReluH{A16, pt1, gf_b});
    gemm_mma<<<gN1, blk256, GEMM_SMEM>>>(A16, ffw, 128, 128, EpiLSTM{hy, cx, ff_b});
}